// round 2
// baseline (speedup 1.0000x reference)
#include <cuda_runtime.h>
#include <cuda_bf16.h>
#include <cstdint>
#include <cstddef>

#define NNODE 50000
#define IN_DIM 32
#define HID 128
#define OUT_DIMS 10
#define KCH 5
#define EPK 400000
#define NEDGE (KCH * EPK)
#define NGROUP 500

// ---------------- scratch (device globals; no allocations allowed) ----------
__device__ float g_xl[6][(size_t)NNODE * HID];   // x_l[0..5]
__device__ float g_h1[(size_t)NNODE * HID];      // inp @ W^T
__device__ float g_xk[(size_t)NNODE * HID];      // per-layer accumulator
__device__ float g_dinv[KCH * NNODE];
__device__ int   g_cnt[KCH * NNODE];
__device__ int   g_rowptr[KCH * (NNODE + 1)];
__device__ int   g_cursor[KCH * NNODE];
__device__ int   g_esrc[NEDGE];
__device__ float g_ecoef[NEDGE];
__device__ float g_pooled[NGROUP * 3 * HID];

// ---------------- packed f32x2 helpers --------------------------------------
__device__ __forceinline__ void fma2(unsigned long long& c, unsigned long long a,
                                     unsigned long long b) {
    asm volatile("fma.rn.f32x2 %0, %1, %2, %0;" : "+l"(c) : "l"(a), "l"(b));
}
__device__ __forceinline__ unsigned long long pack2(float lo, float hi) {
    unsigned long long r;
    asm("mov.b64 %0, {%1, %2};" : "=l"(r) : "f"(lo), "f"(hi));
    return r;
}
__device__ __forceinline__ float2 unpack2(unsigned long long v) {
    float2 r;
    asm("mov.b64 {%0, %1}, %2;" : "=f"(r.x), "=f"(r.y) : "l"(v));
    return r;
}

// ---------------- CSR build -------------------------------------------------
__global__ void count_kernel(const int* __restrict__ kei) {
    int e = blockIdx.x * blockDim.x + threadIdx.x;
    if (e >= NEDGE) return;
    int chunk = e / EPK;
    int d = kei[NEDGE + e];  // dst row
    atomicAdd(&g_cnt[chunk * NNODE + d], 1);
}

__global__ void dinv_kernel() {
    int i = blockIdx.x * blockDim.x + threadIdx.x;
    if (i >= KCH * NNODE) return;
    g_dinv[i] = rsqrtf((float)g_cnt[i] + 1.0f);
}

__global__ void scan_kernel() {
    // one block per chunk, exclusive prefix over 50000 counts
    int c = blockIdx.x;
    int tid = threadIdx.x;
    __shared__ int buf[1024];
    __shared__ int carry_s;
    const int* cnt = g_cnt + c * NNODE;
    int* rowp = g_rowptr + c * (NNODE + 1);
    int* curs = g_cursor + c * NNODE;
    if (tid == 0) carry_s = 0;
    __syncthreads();
    for (int base = 0; base < NNODE; base += 1024) {
        int i = base + tid;
        int v = (i < NNODE) ? cnt[i] : 0;
        buf[tid] = v;
        __syncthreads();
        for (int off = 1; off < 1024; off <<= 1) {
            int t = (tid >= off) ? buf[tid - off] : 0;
            __syncthreads();
            buf[tid] += t;
            __syncthreads();
        }
        int incl = buf[tid];
        int carry = carry_s;
        if (i < NNODE) {
            int excl = carry + incl - v;
            rowp[i] = excl;
            curs[i] = excl;
        }
        __syncthreads();
        if (tid == 1023) carry_s = carry + incl;
        __syncthreads();
    }
    if (tid == 0) rowp[NNODE] = carry_s;
}

__global__ void scatter_kernel(const int* __restrict__ kei) {
    int e = blockIdx.x * blockDim.x + threadIdx.x;
    if (e >= NEDGE) return;
    int chunk = e / EPK;
    int s = kei[e];
    int d = kei[NEDGE + e];
    int pos = atomicAdd(&g_cursor[chunk * NNODE + d], 1);
    g_esrc[(size_t)chunk * EPK + pos] = s;
    g_ecoef[(size_t)chunk * EPK + pos] =
        g_dinv[chunk * NNODE + s] * g_dinv[chunk * NNODE + d];
}

// ---------------- GEMM: C[M][128] = A[M][K] @ W[128][K]^T (+ bias) ---------
template <int K>
__global__ __launch_bounds__(256) void gemm_kernel(
    const float* __restrict__ A, const float* __restrict__ W,
    const float* __restrict__ bias, float* __restrict__ C, int M) {
    constexpr int BM = 64, BK = 32;
    __shared__ float As[BK][68];    // [k][m], padded: 16B-aligned rows
    __shared__ float Bs[BK][132];   // [k][col], padded: 8B-aligned rows

    int tid = threadIdx.x;
    int tx = tid & 31;   // col quad: cols 4*tx..4*tx+3
    int ty = tid >> 5;   // row octet: rows 8*ty..8*ty+7
    int m0 = blockIdx.x * BM;

    unsigned long long acc[8][2];
#pragma unroll
    for (int i = 0; i < 8; i++) { acc[i][0] = 0ull; acc[i][1] = 0ull; }

    for (int k0 = 0; k0 < K; k0 += BK) {
        // A tile: 64 rows x 32 k
        {
            int r = tid >> 3;
            int kc = (tid & 7) * 4;
#pragma unroll
            for (int p = 0; p < 2; p++) {
                int row = m0 + r + p * 32;
                int rowc = row < M ? row : (M - 1);
                float4 v = *reinterpret_cast<const float4*>(A + (size_t)rowc * K + k0 + kc);
                As[kc + 0][r + p * 32] = v.x;
                As[kc + 1][r + p * 32] = v.y;
                As[kc + 2][r + p * 32] = v.z;
                As[kc + 3][r + p * 32] = v.w;
            }
            // B tile: 128 cols x 32 k (transpose on store)
            int col = tid >> 1;
            int kb = (tid & 1) * 16;
#pragma unroll
            for (int p = 0; p < 4; p++) {
                float4 v = *reinterpret_cast<const float4*>(W + (size_t)col * K + k0 + kb + p * 4);
                Bs[kb + p * 4 + 0][col] = v.x;
                Bs[kb + p * 4 + 1][col] = v.y;
                Bs[kb + p * 4 + 2][col] = v.z;
                Bs[kb + p * 4 + 3][col] = v.w;
            }
        }
        __syncthreads();
#pragma unroll
        for (int k = 0; k < BK; k++) {
            float4 a0 = *reinterpret_cast<const float4*>(&As[k][ty * 8]);
            float4 a1 = *reinterpret_cast<const float4*>(&As[k][ty * 8 + 4]);
            unsigned long long b0 = *reinterpret_cast<const unsigned long long*>(&Bs[k][tx * 4]);
            unsigned long long b1 = *reinterpret_cast<const unsigned long long*>(&Bs[k][tx * 4 + 2]);
            float av[8] = {a0.x, a0.y, a0.z, a0.w, a1.x, a1.y, a1.z, a1.w};
#pragma unroll
            for (int i = 0; i < 8; i++) {
                unsigned long long pa = pack2(av[i], av[i]);
                fma2(acc[i][0], pa, b0);
                fma2(acc[i][1], pa, b1);
            }
        }
        __syncthreads();
    }

    float4 bv = make_float4(0.f, 0.f, 0.f, 0.f);
    if (bias) bv = *reinterpret_cast<const float4*>(bias + tx * 4);
#pragma unroll
    for (int i = 0; i < 8; i++) {
        int row = m0 + ty * 8 + i;
        if (row < M) {
            float2 lo = unpack2(acc[i][0]);
            float2 hi = unpack2(acc[i][1]);
            float4 o = make_float4(lo.x + bv.x, lo.y + bv.y, hi.x + bv.z, hi.y + bv.w);
            *reinterpret_cast<float4*>(C + (size_t)row * HID + tx * 4) = o;
        }
    }
}

// ---------------- GCN aggregation: one warp per dst node --------------------
__global__ __launch_bounds__(256) void agg_kernel(
    const float* __restrict__ h1, const float* __restrict__ dinv,
    const int* __restrict__ rp, const int* __restrict__ esrc,
    const float* __restrict__ ecoef, const float* __restrict__ bias,
    float invk, float* __restrict__ xk, float* __restrict__ hout,
    int first, int last) {
    int w = (blockIdx.x * blockDim.x + threadIdx.x) >> 5;
    int lane = threadIdx.x & 31;
    if (w >= NNODE) return;
    int beg = rp[w], end = rp[w + 1];
    float4 acc = make_float4(0.f, 0.f, 0.f, 0.f);
    for (int b = beg; b < end; b += 32) {
        int e = b + lane;
        int s = 0;
        float cf = 0.f;
        if (e < end) { s = esrc[e]; cf = ecoef[e]; }
        int cnt = min(32, end - b);
        for (int j = 0; j < cnt; j++) {
            int ss = __shfl_sync(0xffffffffu, s, j);
            float cc = __shfl_sync(0xffffffffu, cf, j);
            float4 v = *reinterpret_cast<const float4*>(h1 + (size_t)ss * HID + lane * 4);
            acc.x = fmaf(cc, v.x, acc.x);
            acc.y = fmaf(cc, v.y, acc.y);
            acc.z = fmaf(cc, v.z, acc.z);
            acc.w = fmaf(cc, v.w, acc.w);
        }
    }
    float di = dinv[w];
    float sc = di * di;
    float4 hv = *reinterpret_cast<const float4*>(h1 + (size_t)w * HID + lane * 4);
    float4 bv = *reinterpret_cast<const float4*>(bias + lane * 4);
    acc.x = (acc.x + sc * hv.x + bv.x) * invk;
    acc.y = (acc.y + sc * hv.y + bv.y) * invk;
    acc.z = (acc.z + sc * hv.z + bv.z) * invk;
    acc.w = (acc.w + sc * hv.w + bv.w) * invk;

    float* xp = xk + (size_t)w * HID + lane * 4;
    float4 tot = acc;
    if (!first) {
        float4 p = *reinterpret_cast<float4*>(xp);
        tot.x += p.x; tot.y += p.y; tot.z += p.z; tot.w += p.w;
    }
    if (last) {
        float4 r = make_float4(fmaxf(tot.x, 0.f), fmaxf(tot.y, 0.f),
                               fmaxf(tot.z, 0.f), fmaxf(tot.w, 0.f));
        *reinterpret_cast<float4*>(hout + (size_t)w * HID + lane * 4) = r;
    } else {
        *reinterpret_cast<float4*>(xp) = tot;
    }
}

// ---------------- pooling: one block per group (batch is sorted) -----------
__global__ void pool_kernel(const int* __restrict__ batch,
                            const float* __restrict__ h,
                            float* __restrict__ pooled) {
    int g = blockIdx.x;
    int c = threadIdx.x;
    __shared__ int s_lo, s_hi;
    if (c == 0) {
        int lo = 0, hi = NNODE;
        while (lo < hi) { int m = (lo + hi) >> 1; if (batch[m] < g) lo = m + 1; else hi = m; }
        s_lo = lo;
        int lo2 = lo, hi2 = NNODE;
        while (lo2 < hi2) { int m = (lo2 + hi2) >> 1; if (batch[m] < g + 1) lo2 = m + 1; else hi2 = m; }
        s_hi = lo2;
    }
    __syncthreads();
    int lo = s_lo, hi = s_hi;
    float s = 0.f, mx = -3.402823466e38f;
    for (int i = lo; i < hi; i++) {
        float v = h[(size_t)i * HID + c];
        s += v;
        mx = fmaxf(mx, v);
    }
    float cntf = (float)(hi - lo);
    pooled[g * 384 + c] = s;
    pooled[g * 384 + 128 + c] = mx;
    pooled[g * 384 + 256 + c] = s / fmaxf(cntf, 1.f);
}

// ---------------- MLP head: one block per group -----------------------------
__global__ void mlp_kernel(const float* __restrict__ pooled,
                           const float* __restrict__ r1W, const float* __restrict__ r1b,
                           const float* __restrict__ r2W, const float* __restrict__ r2b,
                           float* __restrict__ out) {
    int g = blockIdx.x;
    int j = threadIdx.x;  // 192 threads
    __shared__ float sp[384];
    __shared__ float sh[192];
    for (int t = j; t < 384; t += 192) sp[t] = pooled[g * 384 + t];
    __syncthreads();
    float acc = r1b[j];
    const float* wr = r1W + (size_t)j * 384;
#pragma unroll 4
    for (int t = 0; t < 384; t++) acc = fmaf(sp[t], wr[t], acc);
    sh[j] = acc > 0.f ? acc : 0.01f * acc;
    __syncthreads();
    if (j < OUT_DIMS) {
        float a2 = r2b[j];
        const float* w2 = r2W + (size_t)j * 192;
#pragma unroll 4
        for (int t = 0; t < 192; t++) a2 = fmaf(sh[t], w2[t], a2);
        out[g * OUT_DIMS + j] = a2;
    }
}

// ---------------- launch ----------------------------------------------------
extern "C" void kernel_launch(void* const* d_in, const int* in_sizes, int n_in,
                              void* d_out, int out_size) {
    const float* x      = (const float*)d_in[0];
    const int*   kei    = (const int*)d_in[1];
    // d_in[2] = k_idx (unused in forward)
    const int*   batch  = (const int*)d_in[3];
    const float* emb_W  = (const float*)d_in[4];
    const float* emb_b  = (const float*)d_in[5];
    const float* conv_W = (const float*)d_in[6];
    const float* conv_b = (const float*)d_in[7];
    const float* r1_W   = (const float*)d_in[8];
    const float* r1_b   = (const float*)d_in[9];
    const float* r2_W   = (const float*)d_in[10];
    const float* r2_b   = (const float*)d_in[11];
    float* out = (float*)d_out;

    float *xl, *h1, *xk, *pooled;
    int* cntp;
    cudaGetSymbolAddress((void**)&xl, g_xl);
    cudaGetSymbolAddress((void**)&h1, g_h1);
    cudaGetSymbolAddress((void**)&xk, g_xk);
    cudaGetSymbolAddress((void**)&pooled, g_pooled);
    cudaGetSymbolAddress((void**)&cntp, g_cnt);
    float* dinvp; cudaGetSymbolAddress((void**)&dinvp, g_dinv);
    int* rowptr;  cudaGetSymbolAddress((void**)&rowptr, g_rowptr);
    int* esrc;    cudaGetSymbolAddress((void**)&esrc, g_esrc);
    float* ecoef; cudaGetSymbolAddress((void**)&ecoef, g_ecoef);

    // CSR build (per launch; deterministic work)
    cudaMemsetAsync(cntp, 0, sizeof(int) * KCH * NNODE);
    count_kernel<<<(NEDGE + 255) / 256, 256>>>(kei);
    dinv_kernel<<<(KCH * NNODE + 255) / 256, 256>>>();
    scan_kernel<<<KCH, 1024>>>();
    scatter_kernel<<<(NEDGE + 255) / 256, 256>>>(kei);

    const int gemm_grid = (NNODE + 63) / 64;
    const int agg_grid = (NNODE * 32 + 255) / 256;

    // embedding: xl[0] = x @ emb_W^T + emb_b
    gemm_kernel<IN_DIM><<<gemm_grid, 256>>>(x, emb_W, emb_b, xl, NNODE);

    int ci = 0;
    for (int l = 0; l < 5; l++) {
        for (int k = 1; k <= l + 1; k++, ci++) {
            const float* inp = xl + (size_t)(l + 1 - k) * NNODE * HID;
            gemm_kernel<HID><<<gemm_grid, 256>>>(
                inp, conv_W + (size_t)ci * HID * HID, nullptr, h1, NNODE);
            int chunk = k - 1;
            agg_kernel<<<agg_grid, 256>>>(
                h1, dinvp + chunk * NNODE, rowptr + chunk * (NNODE + 1),
                esrc + (size_t)chunk * EPK, ecoef + (size_t)chunk * EPK,
                conv_b + (size_t)ci * HID, 1.0f / (float)k, xk,
                xl + (size_t)(l + 1) * NNODE * HID,
                (k == 1) ? 1 : 0, (k == l + 1) ? 1 : 0);
        }
    }

    pool_kernel<<<NGROUP, HID>>>(batch, xl + (size_t)5 * NNODE * HID, pooled);
    mlp_kernel<<<NGROUP, 192>>>(pooled, r1_W, r1_b, r2_W, r2_b, out);
}

// round 8
// speedup vs baseline: 1.0903x; 1.0903x over previous
#include <cuda_runtime.h>
#include <cuda_bf16.h>
#include <cstdint>
#include <cstddef>

#define NNODE 50000
#define IN_DIM 32
#define HID 128
#define OUT_DIMS 10
#define KCH 5
#define EPK 400000
#define NEDGE (KCH * EPK)
#define NGROUP 500
#define SCAN_BLOCKS 25   // ceil(50000/2048)

// ---------------- scratch (device globals; no allocations allowed) ----------
__device__ float g_xl[6][(size_t)NNODE * HID];   // x_l[0..5]
__device__ float g_h1[(size_t)NNODE * HID];      // inp @ W^T
__device__ float g_xk[(size_t)NNODE * HID];      // per-layer accumulator
__device__ float g_dinv[KCH * NNODE];
__device__ int   g_cnt[KCH * NNODE];
__device__ int   g_rowptr[KCH * (NNODE + 1)];
__device__ int   g_cursor[KCH * NNODE];
__device__ int   g_bsum[KCH * SCAN_BLOCKS];
__device__ int   g_esrc[NEDGE];
__device__ float g_ecoef[NEDGE];
__device__ float g_pooled[NGROUP * 3 * HID];

// ---------------- CSR build -------------------------------------------------
__global__ void count_kernel(const int* __restrict__ kei) {
    int e = blockIdx.x * blockDim.x + threadIdx.x;
    if (e >= NEDGE) return;
    int chunk = e / EPK;
    int d = kei[NEDGE + e];
    atomicAdd(&g_cnt[chunk * NNODE + d], 1);
}

__global__ void dinv_kernel() {
    int i = blockIdx.x * blockDim.x + threadIdx.x;
    if (i >= KCH * NNODE) return;
    g_dinv[i] = rsqrtf((float)g_cnt[i] + 1.0f);
}

__global__ void scan1_kernel() {
    int ch = blockIdx.y, bx = blockIdx.x, tid = threadIdx.x;
    const int* cnt = g_cnt + ch * NNODE;
    int base = bx * 2048 + tid * 8;
    int tot = 0;
#pragma unroll
    for (int i = 0; i < 8; i++) { int idx = base + i; if (idx < NNODE) tot += cnt[idx]; }
    __shared__ int s[256];
    s[tid] = tot; __syncthreads();
    for (int off = 128; off > 0; off >>= 1) {
        if (tid < off) s[tid] += s[tid + off];
        __syncthreads();
    }
    if (tid == 0) g_bsum[ch * SCAN_BLOCKS + bx] = s[0];
}

__global__ void scan2_kernel() {
    int c = threadIdx.x;
    if (c >= KCH) return;
    int run = 0;
    for (int b = 0; b < SCAN_BLOCKS; b++) {
        int t = g_bsum[c * SCAN_BLOCKS + b];
        g_bsum[c * SCAN_BLOCKS + b] = run;
        run += t;
    }
    g_rowptr[c * (NNODE + 1) + NNODE] = run;
}

__global__ void scan3_kernel() {
    int ch = blockIdx.y, bx = blockIdx.x, tid = threadIdx.x;
    const int* cnt = g_cnt + ch * NNODE;
    int base = bx * 2048 + tid * 8;
    int v[8]; int tot = 0;
#pragma unroll
    for (int i = 0; i < 8; i++) {
        int idx = base + i;
        v[i] = (idx < NNODE) ? cnt[idx] : 0;
        tot += v[i];
    }
    __shared__ int s[256];
    s[tid] = tot; __syncthreads();
    for (int off = 1; off < 256; off <<= 1) {
        int t = (tid >= off) ? s[tid - off] : 0;
        __syncthreads();
        s[tid] += t;
        __syncthreads();
    }
    int excl = s[tid] - tot + g_bsum[ch * SCAN_BLOCKS + bx];
    int* rowp = g_rowptr + ch * (NNODE + 1);
    int* curs = g_cursor + ch * NNODE;
#pragma unroll
    for (int i = 0; i < 8; i++) {
        int idx = base + i;
        if (idx < NNODE) { rowp[idx] = excl; curs[idx] = excl; }
        excl += v[i];
    }
}

__global__ void scatter_kernel(const int* __restrict__ kei) {
    int e = blockIdx.x * blockDim.x + threadIdx.x;
    if (e >= NEDGE) return;
    int chunk = e / EPK;
    int s = kei[e];
    int d = kei[NEDGE + e];
    int pos = atomicAdd(&g_cursor[chunk * NNODE + d], 1);
    g_esrc[(size_t)chunk * EPK + pos] = s;
    g_ecoef[(size_t)chunk * EPK + pos] =
        g_dinv[chunk * NNODE + s] * g_dinv[chunk * NNODE + d];
}

// ---------------- split-bf16 mma.sync GEMM ----------------------------------
// C[M][128] = A[M][K] @ W[128][K]^T (+bias), error-compensated bf16:
//   D = Ahi*Whi + Alo*Whi + Ahi*Wlo       (drops only lo*lo ~ 2^-18)
// mma.sync.aligned.m16n8k16.row.col.f32.bf16.bf16.f32 (sm_80+ legacy path —
// compiles on plain sm_103 target; tcgen05 does NOT).
__device__ __forceinline__ void mma_bf16(float* c, const uint32_t* a,
                                         uint32_t b0, uint32_t b1) {
    asm volatile(
        "mma.sync.aligned.m16n8k16.row.col.f32.bf16.bf16.f32 "
        "{%0,%1,%2,%3}, {%4,%5,%6,%7}, {%8,%9}, {%0,%1,%2,%3};"
        : "+f"(c[0]), "+f"(c[1]), "+f"(c[2]), "+f"(c[3])
        : "r"(a[0]), "r"(a[1]), "r"(a[2]), "r"(a[3]), "r"(b0), "r"(b1));
}

template <int K>
__global__ __launch_bounds__(256) void gemm_mma(
    const float* __restrict__ A, const float* __restrict__ W,
    const float* __restrict__ bias, float* __restrict__ C, int M) {
    constexpr int KW = (K + 8) / 2;     // u32 words per padded bf16 row
    constexpr int NKC = K / 16;         // k-chunks of 16

    // dynamic smem: Whi[128*KW] Wlo[128*KW] Ahi[64*KW] Alo[64*KW] (u32 words)
    extern __shared__ uint32_t sm[];
    uint32_t* Whi = sm;
    uint32_t* Wlo = Whi + 128 * KW;
    uint32_t* Ahi = Wlo + 128 * KW;
    uint32_t* Alo = Ahi + 64 * KW;

    int tid = threadIdx.x;
    int lane = tid & 31, warp = tid >> 5;
    int wm = warp >> 1, wn = warp & 1;  // warp tile: rows wm*16.., cols wn*64..
    int m0 = blockIdx.x * 64;

    // W (128 x K) -> hi/lo bf16x2
    for (int idx = tid; idx < 128 * (K / 2); idx += 256) {
        int n = idx / (K / 2), cp = idx % (K / 2);
        float2 v = *reinterpret_cast<const float2*>(W + (size_t)n * K + cp * 2);
        __nv_bfloat162 h = __floats2bfloat162_rn(v.x, v.y);
        float hx = __bfloat162float(h.x), hy = __bfloat162float(h.y);
        __nv_bfloat162 l = __floats2bfloat162_rn(v.x - hx, v.y - hy);
        Whi[n * KW + cp] = *reinterpret_cast<uint32_t*>(&h);
        Wlo[n * KW + cp] = *reinterpret_cast<uint32_t*>(&l);
    }
    // A tile (64 x K) -> hi/lo bf16x2
    for (int idx = tid; idx < 64 * (K / 2); idx += 256) {
        int r = idx / (K / 2), cp = idx % (K / 2);
        int row = m0 + r; if (row >= M) row = M - 1;
        float2 v = *reinterpret_cast<const float2*>(A + (size_t)row * K + cp * 2);
        __nv_bfloat162 h = __floats2bfloat162_rn(v.x, v.y);
        float hx = __bfloat162float(h.x), hy = __bfloat162float(h.y);
        __nv_bfloat162 l = __floats2bfloat162_rn(v.x - hx, v.y - hy);
        Ahi[r * KW + cp] = *reinterpret_cast<uint32_t*>(&h);
        Alo[r * KW + cp] = *reinterpret_cast<uint32_t*>(&l);
    }
    __syncthreads();

    float c[8][4];
#pragma unroll
    for (int i = 0; i < 8; i++)
#pragma unroll
        for (int j = 0; j < 4; j++) c[i][j] = 0.f;

    int g = lane >> 2, t = lane & 3;

#pragma unroll
    for (int kc = 0; kc < NKC; kc++) {
        // A fragments (canonical m16n8k16 row-major mapping):
        // a0: row g,   k = kc*16 + t*2      a1: row g+8, same k
        // a2: row g,   k = kc*16 + 8 + t*2  a3: row g+8, same k
        uint32_t ah[4], al[4];
        int ab = (wm * 16 + g) * KW + kc * 8 + t;
        ah[0] = Ahi[ab];             al[0] = Alo[ab];
        ah[1] = Ahi[ab + 8 * KW];    al[1] = Alo[ab + 8 * KW];
        ah[2] = Ahi[ab + 4];         al[2] = Alo[ab + 4];
        ah[3] = Ahi[ab + 8 * KW + 4];al[3] = Alo[ab + 8 * KW + 4];
#pragma unroll
        for (int nt = 0; nt < 8; nt++) {
            // B fragments (col-major K x N = W[n][k]):
            // b0: col n, k = kc*16 + t*2   b1: col n, k = kc*16 + 8 + t*2
            int n = wn * 64 + nt * 8 + g;
            int bb = n * KW + kc * 8 + t;
            uint32_t bh0 = Whi[bb], bh1 = Whi[bb + 4];
            uint32_t bl0 = Wlo[bb], bl1 = Wlo[bb + 4];
            mma_bf16(c[nt], ah, bh0, bh1);
            mma_bf16(c[nt], al, bh0, bh1);
            mma_bf16(c[nt], ah, bl0, bl1);
        }
    }

    // epilogue: c{0,1} -> row g, cols t*2,t*2+1 ; c{2,3} -> row g+8
    int r0 = m0 + wm * 16 + g;
    int r1 = r0 + 8;
#pragma unroll
    for (int nt = 0; nt < 8; nt++) {
        int col = wn * 64 + nt * 8 + t * 2;
        float bx = 0.f, by = 0.f;
        if (bias) { bx = bias[col]; by = bias[col + 1]; }
        if (r0 < M) {
            float2 o = make_float2(c[nt][0] + bx, c[nt][1] + by);
            *reinterpret_cast<float2*>(C + (size_t)r0 * HID + col) = o;
        }
        if (r1 < M) {
            float2 o = make_float2(c[nt][2] + bx, c[nt][3] + by);
            *reinterpret_cast<float2*>(C + (size_t)r1 * HID + col) = o;
        }
    }
}

// ---------------- GCN aggregation: one warp per dst node --------------------
__global__ __launch_bounds__(256) void agg_kernel(
    const float* __restrict__ h1, const float* __restrict__ dinv,
    const int* __restrict__ rp, const int* __restrict__ esrc,
    const float* __restrict__ ecoef, const float* __restrict__ bias,
    float invk, float* __restrict__ xk, float* __restrict__ hout,
    int first, int last) {
    int w = (blockIdx.x * blockDim.x + threadIdx.x) >> 5;
    int lane = threadIdx.x & 31;
    if (w >= NNODE) return;
    int beg = rp[w], end = rp[w + 1];
    float4 acc = make_float4(0.f, 0.f, 0.f, 0.f);
    for (int b = beg; b < end; b += 32) {
        int e = b + lane;
        int s = 0;
        float cf = 0.f;
        if (e < end) { s = esrc[e]; cf = ecoef[e]; }
        int cnt = min(32, end - b);
        for (int j = 0; j < cnt; j++) {
            int ss = __shfl_sync(0xffffffffu, s, j);
            float cc = __shfl_sync(0xffffffffu, cf, j);
            float4 v = *reinterpret_cast<const float4*>(h1 + (size_t)ss * HID + lane * 4);
            acc.x = fmaf(cc, v.x, acc.x);
            acc.y = fmaf(cc, v.y, acc.y);
            acc.z = fmaf(cc, v.z, acc.z);
            acc.w = fmaf(cc, v.w, acc.w);
        }
    }
    float di = dinv[w];
    float sc = di * di;
    float4 hv = *reinterpret_cast<const float4*>(h1 + (size_t)w * HID + lane * 4);
    float4 bv = *reinterpret_cast<const float4*>(bias + lane * 4);
    acc.x = (acc.x + sc * hv.x + bv.x) * invk;
    acc.y = (acc.y + sc * hv.y + bv.y) * invk;
    acc.z = (acc.z + sc * hv.z + bv.z) * invk;
    acc.w = (acc.w + sc * hv.w + bv.w) * invk;

    float* xp = xk + (size_t)w * HID + lane * 4;
    float4 tot = acc;
    if (!first) {
        float4 p = *reinterpret_cast<float4*>(xp);
        tot.x += p.x; tot.y += p.y; tot.z += p.z; tot.w += p.w;
    }
    if (last) {
        float4 r = make_float4(fmaxf(tot.x, 0.f), fmaxf(tot.y, 0.f),
                               fmaxf(tot.z, 0.f), fmaxf(tot.w, 0.f));
        *reinterpret_cast<float4*>(hout + (size_t)w * HID + lane * 4) = r;
    } else {
        *reinterpret_cast<float4*>(xp) = tot;
    }
}

// ---------------- pooling ----------------------------------------------------
__global__ void pool_kernel(const int* __restrict__ batch,
                            const float* __restrict__ h,
                            float* __restrict__ pooled) {
    int g = blockIdx.x;
    int c = threadIdx.x;
    __shared__ int s_lo, s_hi;
    if (c == 0) {
        int lo = 0, hi = NNODE;
        while (lo < hi) { int m = (lo + hi) >> 1; if (batch[m] < g) lo = m + 1; else hi = m; }
        s_lo = lo;
        int lo2 = lo, hi2 = NNODE;
        while (lo2 < hi2) { int m = (lo2 + hi2) >> 1; if (batch[m] < g + 1) lo2 = m + 1; else hi2 = m; }
        s_hi = lo2;
    }
    __syncthreads();
    int lo = s_lo, hi = s_hi;
    float s = 0.f, mx = -3.402823466e38f;
    for (int i = lo; i < hi; i++) {
        float v = h[(size_t)i * HID + c];
        s += v;
        mx = fmaxf(mx, v);
    }
    float cntf = (float)(hi - lo);
    pooled[g * 384 + c] = s;
    pooled[g * 384 + 128 + c] = mx;
    pooled[g * 384 + 256 + c] = s / fmaxf(cntf, 1.f);
}

// ---------------- MLP head ---------------------------------------------------
__global__ void mlp_kernel(const float* __restrict__ pooled,
                           const float* __restrict__ r1W, const float* __restrict__ r1b,
                           const float* __restrict__ r2W, const float* __restrict__ r2b,
                           float* __restrict__ out) {
    int g = blockIdx.x;
    int j = threadIdx.x;  // 192 threads
    __shared__ float sp[384];
    __shared__ float sh[192];
    for (int t = j; t < 384; t += 192) sp[t] = pooled[g * 384 + t];
    __syncthreads();
    float acc = r1b[j];
    const float* wr = r1W + (size_t)j * 384;
#pragma unroll 4
    for (int t = 0; t < 384; t++) acc = fmaf(sp[t], wr[t], acc);
    sh[j] = acc > 0.f ? acc : 0.01f * acc;
    __syncthreads();
    if (j < OUT_DIMS) {
        float a2 = r2b[j];
        const float* w2 = r2W + (size_t)j * 192;
#pragma unroll 4
        for (int t = 0; t < 192; t++) a2 = fmaf(sh[t], w2[t], a2);
        out[g * OUT_DIMS + j] = a2;
    }
}

// ---------------- launch ----------------------------------------------------
extern "C" void kernel_launch(void* const* d_in, const int* in_sizes, int n_in,
                              void* d_out, int out_size) {
    const float* x      = (const float*)d_in[0];
    const int*   kei    = (const int*)d_in[1];
    const int*   batch  = (const int*)d_in[3];
    const float* emb_W  = (const float*)d_in[4];
    const float* emb_b  = (const float*)d_in[5];
    const float* conv_W = (const float*)d_in[6];
    const float* conv_b = (const float*)d_in[7];
    const float* r1_W   = (const float*)d_in[8];
    const float* r1_b   = (const float*)d_in[9];
    const float* r2_W   = (const float*)d_in[10];
    const float* r2_b   = (const float*)d_in[11];
    float* out = (float*)d_out;

    float *xl, *h1, *xk, *pooled;
    int* cntp;
    cudaGetSymbolAddress((void**)&xl, g_xl);
    cudaGetSymbolAddress((void**)&h1, g_h1);
    cudaGetSymbolAddress((void**)&xk, g_xk);
    cudaGetSymbolAddress((void**)&pooled, g_pooled);
    cudaGetSymbolAddress((void**)&cntp, g_cnt);
    float* dinvp; cudaGetSymbolAddress((void**)&dinvp, g_dinv);
    int* rowptr;  cudaGetSymbolAddress((void**)&rowptr, g_rowptr);
    int* esrc;    cudaGetSymbolAddress((void**)&esrc, g_esrc);
    float* ecoef; cudaGetSymbolAddress((void**)&ecoef, g_ecoef);

    // dynamic smem: (2*128 + 2*64) * KW * 4 bytes
    const int SMEM128 = 384 * ((128 + 8) / 2) * 4;   // 104448 B
    const int SMEM32  = 384 * ((32 + 8) / 2) * 4;    // 30720 B
    cudaFuncSetAttribute(gemm_mma<HID>, cudaFuncAttributeMaxDynamicSharedMemorySize, SMEM128);
    cudaFuncSetAttribute(gemm_mma<IN_DIM>, cudaFuncAttributeMaxDynamicSharedMemorySize, SMEM32);

    // CSR build (per launch; deterministic work)
    cudaMemsetAsync(cntp, 0, sizeof(int) * KCH * NNODE);
    count_kernel<<<(NEDGE + 255) / 256, 256>>>(kei);
    dinv_kernel<<<(KCH * NNODE + 255) / 256, 256>>>();
    dim3 sg(SCAN_BLOCKS, KCH);
    scan1_kernel<<<sg, 256>>>();
    scan2_kernel<<<1, 32>>>();
    scan3_kernel<<<sg, 256>>>();
    scatter_kernel<<<(NEDGE + 255) / 256, 256>>>(kei);

    const int mtiles = (NNODE + 63) / 64;           // 782
    const int agg_grid = (NNODE * 32 + 255) / 256;

    // embedding: xl[0] = x @ emb_W^T + emb_b
    gemm_mma<IN_DIM><<<mtiles, 256, SMEM32>>>(x, emb_W, emb_b, xl, NNODE);

    int ci = 0;
    for (int l = 0; l < 5; l++) {
        for (int k = 1; k <= l + 1; k++, ci++) {
            const float* inp = xl + (size_t)(l + 1 - k) * NNODE * HID;
            gemm_mma<HID><<<mtiles, 256, SMEM128>>>(
                inp, conv_W + (size_t)ci * HID * HID, nullptr, h1, NNODE);
            int chunk = k - 1;
            agg_kernel<<<agg_grid, 256>>>(
                h1, dinvp + chunk * NNODE, rowptr + chunk * (NNODE + 1),
                esrc + (size_t)chunk * EPK, ecoef + (size_t)chunk * EPK,
                conv_b + (size_t)ci * HID, 1.0f / (float)k, xk,
                xl + (size_t)(l + 1) * NNODE * HID,
                (k == 1) ? 1 : 0, (k == l + 1) ? 1 : 0);
        }
    }

    pool_kernel<<<NGROUP, HID>>>(batch, xl + (size_t)5 * NNODE * HID, pooled);
    mlp_kernel<<<NGROUP, 192>>>(pooled, r1_W, r1_b, r2_W, r2_b, out);
}

// round 9
// speedup vs baseline: 1.2980x; 1.1905x over previous
#include <cuda_runtime.h>
#include <cuda_bf16.h>
#include <cstdint>
#include <cstddef>

#define NNODE 50000
#define IN_DIM 32
#define HID 128
#define OUT_DIMS 10
#define KCH 5
#define EPK 400000
#define NEDGE (KCH * EPK)
#define NGROUP 500
#define SCAN_BLOCKS 25   // ceil(50000/2048)

// ---------------- scratch (device globals; no allocations allowed) ----------
__device__ float g_xl[6][(size_t)NNODE * HID];     // x_l[0..5] float (pool needs [5])
__device__ float g_h1[(size_t)NNODE * HID];        // inp @ W^T (GEMM out, agg in)
__device__ float g_xk[(size_t)NNODE * HID];        // per-layer accumulator
__device__ uint32_t g_hbh[6][(size_t)NNODE * 64];  // x_l bf16-hi (bf16x2 words)
__device__ uint32_t g_hbl[6][(size_t)NNODE * 64];  // x_l bf16-lo
__device__ uint32_t g_xbh[(size_t)NNODE * 16];     // x bf16-hi (K=32)
__device__ uint32_t g_xbl[(size_t)NNODE * 16];
__device__ uint32_t g_wembh[128 * 16];             // emb_W bf16 hi/lo
__device__ uint32_t g_wembl[128 * 16];
__device__ uint32_t g_wconvh[15 * 128 * 64];       // conv_W bf16 hi/lo
__device__ uint32_t g_wconvl[15 * 128 * 64];
__device__ float g_dinv[KCH * NNODE];
__device__ int   g_cnt[KCH * NNODE];
__device__ int   g_rowptr[KCH * (NNODE + 1)];
__device__ int   g_cursor[KCH * NNODE];
__device__ int   g_bsum[KCH * SCAN_BLOCKS];
__device__ int   g_esrc[NEDGE];
__device__ float g_ecoef[NEDGE];
__device__ float g_pooled[NGROUP * 3 * HID];

// ---------------- bf16 split helpers ----------------------------------------
__device__ __forceinline__ void split_pair(float x, float y, uint32_t& h, uint32_t& l) {
    __nv_bfloat162 hb = __floats2bfloat162_rn(x, y);
    float hx = __bfloat162float(hb.x), hy = __bfloat162float(hb.y);
    __nv_bfloat162 lb = __floats2bfloat162_rn(x - hx, y - hy);
    h = *reinterpret_cast<uint32_t*>(&hb);
    l = *reinterpret_cast<uint32_t*>(&lb);
}

__global__ void prep_pairs(const float* __restrict__ src, uint32_t* __restrict__ dh,
                           uint32_t* __restrict__ dl, int npairs) {
    int i = blockIdx.x * blockDim.x + threadIdx.x;
    if (i >= npairs) return;
    float2 v = *reinterpret_cast<const float2*>(src + (size_t)i * 2);
    uint32_t h, l;
    split_pair(v.x, v.y, h, l);
    dh[i] = h;
    dl[i] = l;
}

// ---------------- CSR build -------------------------------------------------
__global__ void count_kernel(const int* __restrict__ kei) {
    int e = blockIdx.x * blockDim.x + threadIdx.x;
    if (e >= NEDGE) return;
    int chunk = e / EPK;
    int d = kei[NEDGE + e];
    atomicAdd(&g_cnt[chunk * NNODE + d], 1);
}

__global__ void dinv_kernel() {
    int i = blockIdx.x * blockDim.x + threadIdx.x;
    if (i >= KCH * NNODE) return;
    g_dinv[i] = rsqrtf((float)g_cnt[i] + 1.0f);
}

__global__ void scan1_kernel() {
    int ch = blockIdx.y, bx = blockIdx.x, tid = threadIdx.x;
    const int* cnt = g_cnt + ch * NNODE;
    int base = bx * 2048 + tid * 8;
    int tot = 0;
#pragma unroll
    for (int i = 0; i < 8; i++) { int idx = base + i; if (idx < NNODE) tot += cnt[idx]; }
    __shared__ int s[256];
    s[tid] = tot; __syncthreads();
    for (int off = 128; off > 0; off >>= 1) {
        if (tid < off) s[tid] += s[tid + off];
        __syncthreads();
    }
    if (tid == 0) g_bsum[ch * SCAN_BLOCKS + bx] = s[0];
}

__global__ void scan2_kernel() {
    int c = threadIdx.x;
    if (c >= KCH) return;
    int run = 0;
    for (int b = 0; b < SCAN_BLOCKS; b++) {
        int t = g_bsum[c * SCAN_BLOCKS + b];
        g_bsum[c * SCAN_BLOCKS + b] = run;
        run += t;
    }
    g_rowptr[c * (NNODE + 1) + NNODE] = run;
}

__global__ void scan3_kernel() {
    int ch = blockIdx.y, bx = blockIdx.x, tid = threadIdx.x;
    const int* cnt = g_cnt + ch * NNODE;
    int base = bx * 2048 + tid * 8;
    int v[8]; int tot = 0;
#pragma unroll
    for (int i = 0; i < 8; i++) {
        int idx = base + i;
        v[i] = (idx < NNODE) ? cnt[idx] : 0;
        tot += v[i];
    }
    __shared__ int s[256];
    s[tid] = tot; __syncthreads();
    for (int off = 1; off < 256; off <<= 1) {
        int t = (tid >= off) ? s[tid - off] : 0;
        __syncthreads();
        s[tid] += t;
        __syncthreads();
    }
    int excl = s[tid] - tot + g_bsum[ch * SCAN_BLOCKS + bx];
    int* rowp = g_rowptr + ch * (NNODE + 1);
    int* curs = g_cursor + ch * NNODE;
#pragma unroll
    for (int i = 0; i < 8; i++) {
        int idx = base + i;
        if (idx < NNODE) { rowp[idx] = excl; curs[idx] = excl; }
        excl += v[i];
    }
}

__global__ void scatter_kernel(const int* __restrict__ kei) {
    int e = blockIdx.x * blockDim.x + threadIdx.x;
    if (e >= NEDGE) return;
    int chunk = e / EPK;
    int s = kei[e];
    int d = kei[NEDGE + e];
    int pos = atomicAdd(&g_cursor[chunk * NNODE + d], 1);
    g_esrc[(size_t)chunk * EPK + pos] = s;
    g_ecoef[(size_t)chunk * EPK + pos] =
        g_dinv[chunk * NNODE + s] * g_dinv[chunk * NNODE + d];
}

// ---------------- split-bf16 mma.sync GEMM ----------------------------------
// C[M][128] = A[M][K] @ W[128][K]^T (+bias); A,W pre-split bf16 hi/lo.
//   D = Ahi*Whi + Alo*Whi + Ahi*Wlo
// XOR-swizzled smem (quad ^= row&QM): conflict-free fragment LDS (K=128).
__device__ __forceinline__ void mma_bf16(float* c, const uint32_t* a,
                                         uint32_t b0, uint32_t b1) {
    asm volatile(
        "mma.sync.aligned.m16n8k16.row.col.f32.bf16.bf16.f32 "
        "{%0,%1,%2,%3}, {%4,%5,%6,%7}, {%8,%9}, {%0,%1,%2,%3};"
        : "+f"(c[0]), "+f"(c[1]), "+f"(c[2]), "+f"(c[3])
        : "r"(a[0]), "r"(a[1]), "r"(a[2]), "r"(a[3]), "r"(b0), "r"(b1));
}

template <int K>
__global__ __launch_bounds__(256) void gemm_mma(
    const uint32_t* __restrict__ Ah, const uint32_t* __restrict__ Al,
    const uint32_t* __restrict__ Wh, const uint32_t* __restrict__ Wl,
    const float* __restrict__ bias, float* __restrict__ C,
    uint32_t* __restrict__ Ch, uint32_t* __restrict__ Cl, int M) {
    constexpr int RW = K / 2;                      // u32 words per row
    constexpr int NQ = RW / 4;                     // uint4 quads per row
    constexpr int QM = (NQ >= 8) ? 7 : (NQ - 1);   // swizzle mask
    constexpr int NKC = K / 16;

    extern __shared__ uint32_t sm[];
    uint32_t* sWh = sm;                    // 128*RW
    uint32_t* sWl = sWh + 128 * RW;
    uint32_t* sAh = sWl + 128 * RW;        // 64*RW
    uint32_t* sAl = sAh + 64 * RW;

    int tid = threadIdx.x;
    int lane = tid & 31, warp = tid >> 5;
    int wm = warp >> 1, wn = warp & 1;
    int m0 = blockIdx.x * 64;

    for (int idx = tid; idx < 128 * NQ; idx += 256) {
        int r = idx / NQ, q = idx % NQ;
        int dq = q ^ (r & QM);
        *reinterpret_cast<uint4*>(sWh + r * RW + dq * 4) =
            *reinterpret_cast<const uint4*>(Wh + (size_t)r * RW + q * 4);
        *reinterpret_cast<uint4*>(sWl + r * RW + dq * 4) =
            *reinterpret_cast<const uint4*>(Wl + (size_t)r * RW + q * 4);
    }
    for (int idx = tid; idx < 64 * NQ; idx += 256) {
        int r = idx / NQ, q = idx % NQ;
        int row = m0 + r; if (row >= M) row = M - 1;
        int dq = q ^ (r & QM);
        *reinterpret_cast<uint4*>(sAh + r * RW + dq * 4) =
            *reinterpret_cast<const uint4*>(Ah + (size_t)row * RW + q * 4);
        *reinterpret_cast<uint4*>(sAl + r * RW + dq * 4) =
            *reinterpret_cast<const uint4*>(Al + (size_t)row * RW + q * 4);
    }
    __syncthreads();

    float c[8][4];
#pragma unroll
    for (int i = 0; i < 8; i++)
#pragma unroll
        for (int j = 0; j < 4; j++) c[i][j] = 0.f;

    int g = lane >> 2, t = lane & 3;

    // swizzled word fetch: logical word w of row r
#define LDW(base, r, w) (base)[(r) * RW + (((((w) >> 2) ^ ((r) & QM))) << 2) + ((w) & 3)]

#pragma unroll
    for (int kc = 0; kc < NKC; kc++) {
        int w0 = kc * 8 + t;
        int w1 = kc * 8 + 4 + t;
        int ra = wm * 16 + g;
        uint32_t ah[4], al[4];
        ah[0] = LDW(sAh, ra, w0);     al[0] = LDW(sAl, ra, w0);
        ah[1] = LDW(sAh, ra + 8, w0); al[1] = LDW(sAl, ra + 8, w0);
        ah[2] = LDW(sAh, ra, w1);     al[2] = LDW(sAl, ra, w1);
        ah[3] = LDW(sAh, ra + 8, w1); al[3] = LDW(sAl, ra + 8, w1);
#pragma unroll
        for (int nt = 0; nt < 8; nt++) {
            int n = wn * 64 + nt * 8 + g;
            uint32_t bh0 = LDW(sWh, n, w0), bh1 = LDW(sWh, n, w1);
            uint32_t bl0 = LDW(sWl, n, w0), bl1 = LDW(sWl, n, w1);
            mma_bf16(c[nt], ah, bh0, bh1);
            mma_bf16(c[nt], al, bh0, bh1);
            mma_bf16(c[nt], ah, bl0, bl1);
        }
    }
#undef LDW

    int r0 = m0 + wm * 16 + g;
    int r1 = r0 + 8;
#pragma unroll
    for (int nt = 0; nt < 8; nt++) {
        int col = wn * 64 + nt * 8 + t * 2;
        float bx = 0.f, by = 0.f;
        if (bias) { bx = bias[col]; by = bias[col + 1]; }
        if (r0 < M) {
            float2 o = make_float2(c[nt][0] + bx, c[nt][1] + by);
            *reinterpret_cast<float2*>(C + (size_t)r0 * HID + col) = o;
            if (Ch) {
                uint32_t h, l;
                split_pair(o.x, o.y, h, l);
                Ch[(size_t)r0 * 64 + (col >> 1)] = h;
                Cl[(size_t)r0 * 64 + (col >> 1)] = l;
            }
        }
        if (r1 < M) {
            float2 o = make_float2(c[nt][2] + bx, c[nt][3] + by);
            *reinterpret_cast<float2*>(C + (size_t)r1 * HID + col) = o;
            if (Ch) {
                uint32_t h, l;
                split_pair(o.x, o.y, h, l);
                Ch[(size_t)r1 * 64 + (col >> 1)] = h;
                Cl[(size_t)r1 * 64 + (col >> 1)] = l;
            }
        }
    }
}

// ---------------- GCN aggregation: one warp per dst node --------------------
// uniform-address loads broadcast (s,coef) to the warp; no shfl.
__global__ __launch_bounds__(256) void agg_kernel(
    const float* __restrict__ h1, const float* __restrict__ dinv,
    const int* __restrict__ rp, const int* __restrict__ esrc,
    const float* __restrict__ ecoef, const float* __restrict__ bias,
    float invk, float* __restrict__ xk, float* __restrict__ hout,
    uint32_t* __restrict__ houth, uint32_t* __restrict__ houtl,
    int first, int last) {
    int w = (blockIdx.x * blockDim.x + threadIdx.x) >> 5;
    int lane = threadIdx.x & 31;
    if (w >= NNODE) return;
    int beg = rp[w], end = rp[w + 1];
    float4 a0 = make_float4(0.f, 0.f, 0.f, 0.f);
    float4 a1 = make_float4(0.f, 0.f, 0.f, 0.f);
    int e = beg;
    for (; e + 1 < end; e += 2) {
        int s0 = __ldg(esrc + e), s1 = __ldg(esrc + e + 1);
        float c0 = __ldg(ecoef + e), c1 = __ldg(ecoef + e + 1);
        float4 v0 = *reinterpret_cast<const float4*>(h1 + (size_t)s0 * HID + lane * 4);
        float4 v1 = *reinterpret_cast<const float4*>(h1 + (size_t)s1 * HID + lane * 4);
        a0.x = fmaf(c0, v0.x, a0.x); a0.y = fmaf(c0, v0.y, a0.y);
        a0.z = fmaf(c0, v0.z, a0.z); a0.w = fmaf(c0, v0.w, a0.w);
        a1.x = fmaf(c1, v1.x, a1.x); a1.y = fmaf(c1, v1.y, a1.y);
        a1.z = fmaf(c1, v1.z, a1.z); a1.w = fmaf(c1, v1.w, a1.w);
    }
    if (e < end) {
        int s0 = __ldg(esrc + e);
        float c0 = __ldg(ecoef + e);
        float4 v0 = *reinterpret_cast<const float4*>(h1 + (size_t)s0 * HID + lane * 4);
        a0.x = fmaf(c0, v0.x, a0.x); a0.y = fmaf(c0, v0.y, a0.y);
        a0.z = fmaf(c0, v0.z, a0.z); a0.w = fmaf(c0, v0.w, a0.w);
    }
    float4 acc = make_float4(a0.x + a1.x, a0.y + a1.y, a0.z + a1.z, a0.w + a1.w);

    float di = dinv[w];
    float sc = di * di;
    float4 hv = *reinterpret_cast<const float4*>(h1 + (size_t)w * HID + lane * 4);
    float4 bv = *reinterpret_cast<const float4*>(bias + lane * 4);
    acc.x = (acc.x + sc * hv.x + bv.x) * invk;
    acc.y = (acc.y + sc * hv.y + bv.y) * invk;
    acc.z = (acc.z + sc * hv.z + bv.z) * invk;
    acc.w = (acc.w + sc * hv.w + bv.w) * invk;

    float* xp = xk + (size_t)w * HID + lane * 4;
    float4 tot = acc;
    if (!first) {
        float4 p = *reinterpret_cast<float4*>(xp);
        tot.x += p.x; tot.y += p.y; tot.z += p.z; tot.w += p.w;
    }
    if (last) {
        float4 r = make_float4(fmaxf(tot.x, 0.f), fmaxf(tot.y, 0.f),
                               fmaxf(tot.z, 0.f), fmaxf(tot.w, 0.f));
        *reinterpret_cast<float4*>(hout + (size_t)w * HID + lane * 4) = r;
        uint32_t h0, l0, h1b, l1b;
        split_pair(r.x, r.y, h0, l0);
        split_pair(r.z, r.w, h1b, l1b);
        houth[(size_t)w * 64 + lane * 2] = h0;
        houth[(size_t)w * 64 + lane * 2 + 1] = h1b;
        houtl[(size_t)w * 64 + lane * 2] = l0;
        houtl[(size_t)w * 64 + lane * 2 + 1] = l1b;
    } else {
        *reinterpret_cast<float4*>(xp) = tot;
    }
}

// ---------------- pooling ----------------------------------------------------
__global__ void pool_kernel(const int* __restrict__ batch,
                            const float* __restrict__ h,
                            float* __restrict__ pooled) {
    int g = blockIdx.x;
    int c = threadIdx.x;
    __shared__ int s_lo, s_hi;
    if (c == 0) {
        int lo = 0, hi = NNODE;
        while (lo < hi) { int m = (lo + hi) >> 1; if (batch[m] < g) lo = m + 1; else hi = m; }
        s_lo = lo;
        int lo2 = lo, hi2 = NNODE;
        while (lo2 < hi2) { int m = (lo2 + hi2) >> 1; if (batch[m] < g + 1) lo2 = m + 1; else hi2 = m; }
        s_hi = lo2;
    }
    __syncthreads();
    int lo = s_lo, hi = s_hi;
    float s = 0.f, mx = -3.402823466e38f;
    for (int i = lo; i < hi; i++) {
        float v = h[(size_t)i * HID + c];
        s += v;
        mx = fmaxf(mx, v);
    }
    float cntf = (float)(hi - lo);
    pooled[g * 384 + c] = s;
    pooled[g * 384 + 128 + c] = mx;
    pooled[g * 384 + 256 + c] = s / fmaxf(cntf, 1.f);
}

// ---------------- MLP head ---------------------------------------------------
__global__ void mlp_kernel(const float* __restrict__ pooled,
                           const float* __restrict__ r1W, const float* __restrict__ r1b,
                           const float* __restrict__ r2W, const float* __restrict__ r2b,
                           float* __restrict__ out) {
    int g = blockIdx.x;
    int j = threadIdx.x;  // 192 threads
    __shared__ float sp[384];
    __shared__ float sh[192];
    for (int t = j; t < 384; t += 192) sp[t] = pooled[g * 384 + t];
    __syncthreads();
    float acc = r1b[j];
    const float* wr = r1W + (size_t)j * 384;
#pragma unroll 4
    for (int t = 0; t < 384; t++) acc = fmaf(sp[t], wr[t], acc);
    sh[j] = acc > 0.f ? acc : 0.01f * acc;
    __syncthreads();
    if (j < OUT_DIMS) {
        float a2 = r2b[j];
        const float* w2 = r2W + (size_t)j * 192;
#pragma unroll 4
        for (int t = 0; t < 192; t++) a2 = fmaf(sh[t], w2[t], a2);
        out[g * OUT_DIMS + j] = a2;
    }
}

// ---------------- launch ----------------------------------------------------
extern "C" void kernel_launch(void* const* d_in, const int* in_sizes, int n_in,
                              void* d_out, int out_size) {
    const float* x      = (const float*)d_in[0];
    const int*   kei    = (const int*)d_in[1];
    const int*   batch  = (const int*)d_in[3];
    const float* emb_W  = (const float*)d_in[4];
    const float* emb_b  = (const float*)d_in[5];
    const float* conv_W = (const float*)d_in[6];
    const float* conv_b = (const float*)d_in[7];
    const float* r1_W   = (const float*)d_in[8];
    const float* r1_b   = (const float*)d_in[9];
    const float* r2_W   = (const float*)d_in[10];
    const float* r2_b   = (const float*)d_in[11];
    float* out = (float*)d_out;

    float *xl, *h1, *xk, *pooled, *dinvp, *ecoef;
    int *cntp, *rowptr, *esrc;
    uint32_t *hbh, *hbl, *xbh, *xbl, *wembh, *wembl, *wconvh, *wconvl;
    cudaGetSymbolAddress((void**)&xl, g_xl);
    cudaGetSymbolAddress((void**)&h1, g_h1);
    cudaGetSymbolAddress((void**)&xk, g_xk);
    cudaGetSymbolAddress((void**)&pooled, g_pooled);
    cudaGetSymbolAddress((void**)&cntp, g_cnt);
    cudaGetSymbolAddress((void**)&dinvp, g_dinv);
    cudaGetSymbolAddress((void**)&rowptr, g_rowptr);
    cudaGetSymbolAddress((void**)&esrc, g_esrc);
    cudaGetSymbolAddress((void**)&ecoef, g_ecoef);
    cudaGetSymbolAddress((void**)&hbh, g_hbh);
    cudaGetSymbolAddress((void**)&hbl, g_hbl);
    cudaGetSymbolAddress((void**)&xbh, g_xbh);
    cudaGetSymbolAddress((void**)&xbl, g_xbl);
    cudaGetSymbolAddress((void**)&wembh, g_wembh);
    cudaGetSymbolAddress((void**)&wembl, g_wembl);
    cudaGetSymbolAddress((void**)&wconvh, g_wconvh);
    cudaGetSymbolAddress((void**)&wconvl, g_wconvl);

    const int SMEM128 = (128 * 64 * 2 + 64 * 64 * 2) * 4;   // 98304 B
    const int SMEM32  = (128 * 16 * 2 + 64 * 16 * 2) * 4;   // 24576 B
    cudaFuncSetAttribute(gemm_mma<HID>, cudaFuncAttributeMaxDynamicSharedMemorySize, SMEM128);
    cudaFuncSetAttribute(gemm_mma<IN_DIM>, cudaFuncAttributeMaxDynamicSharedMemorySize, SMEM32);

    // operand prep (bf16 hi/lo splits)
    prep_pairs<<<(NNODE * 16 + 255) / 256, 256>>>(x, xbh, xbl, NNODE * 16);
    prep_pairs<<<(128 * 16 + 255) / 256, 256>>>(emb_W, wembh, wembl, 128 * 16);
    prep_pairs<<<(15 * 128 * 64 + 255) / 256, 256>>>(conv_W, wconvh, wconvl, 15 * 128 * 64);

    // CSR build (per launch; deterministic work)
    cudaMemsetAsync(cntp, 0, sizeof(int) * KCH * NNODE);
    count_kernel<<<(NEDGE + 255) / 256, 256>>>(kei);
    dinv_kernel<<<(KCH * NNODE + 255) / 256, 256>>>();
    dim3 sg(SCAN_BLOCKS, KCH);
    scan1_kernel<<<sg, 256>>>();
    scan2_kernel<<<1, 32>>>();
    scan3_kernel<<<sg, 256>>>();
    scatter_kernel<<<(NEDGE + 255) / 256, 256>>>(kei);

    const int mtiles = (NNODE + 63) / 64;           // 782
    const int agg_grid = (NNODE * 32 + 255) / 256;

    // embedding: x_l[0] = x @ emb_W^T + emb_b  (emit bf16 hi/lo for GEMM input)
    gemm_mma<IN_DIM><<<mtiles, 256, SMEM32>>>(
        xbh, xbl, wembh, wembl, emb_b, xl, hbh, hbl, NNODE);

    int ci = 0;
    for (int l = 0; l < 5; l++) {
        for (int k = 1; k <= l + 1; k++, ci++) {
            int li = l + 1 - k;
            gemm_mma<HID><<<mtiles, 256, SMEM128>>>(
                hbh + (size_t)li * NNODE * 64, hbl + (size_t)li * NNODE * 64,
                wconvh + (size_t)ci * 128 * 64, wconvl + (size_t)ci * 128 * 64,
                nullptr, h1, nullptr, nullptr, NNODE);
            int chunk = k - 1;
            agg_kernel<<<agg_grid, 256>>>(
                h1, dinvp + chunk * NNODE, rowptr + chunk * (NNODE + 1),
                esrc + (size_t)chunk * EPK, ecoef + (size_t)chunk * EPK,
                conv_b + (size_t)ci * HID, 1.0f / (float)k, xk,
                xl + (size_t)(l + 1) * NNODE * HID,
                hbh + (size_t)(l + 1) * NNODE * 64, hbl + (size_t)(l + 1) * NNODE * 64,
                (k == 1) ? 1 : 0, (k == l + 1) ? 1 : 0);
        }
    }

    pool_kernel<<<NGROUP, HID>>>(batch, xl + (size_t)5 * NNODE * HID, pooled);
    mlp_kernel<<<NGROUP, 192>>>(pooled, r1_W, r1_b, r2_W, r2_b, out);
}

// round 11
// speedup vs baseline: 1.4718x; 1.1339x over previous
#include <cuda_runtime.h>
#include <cuda_bf16.h>
#include <cstdint>
#include <cstddef>

#define NNODE 50000
#define IN_DIM 32
#define HID 128
#define OUT_DIMS 10
#define KCH 5
#define EPK 400000
#define NEDGE (KCH * EPK)
#define NGROUP 500
#define SCAN_BLOCKS 25   // ceil(50000/2048)

// ---------------- scratch (device globals; no allocations allowed) ----------
__device__ float g_h1m[KCH][(size_t)NNODE * HID]; // per-k GEMM outputs (layer-local)
__device__ float g_x5[(size_t)NNODE * HID];       // final activations (pool input)
__device__ uint32_t g_hbh[6][(size_t)NNODE * 64]; // x_l bf16-hi (bf16x2 words)
__device__ uint32_t g_hbl[6][(size_t)NNODE * 64]; // x_l bf16-lo
__device__ uint32_t g_xbh[(size_t)NNODE * 16];    // x bf16-hi (K=32)
__device__ uint32_t g_xbl[(size_t)NNODE * 16];
__device__ uint32_t g_wembh[128 * 16];            // emb_W bf16 hi/lo
__device__ uint32_t g_wembl[128 * 16];
__device__ uint32_t g_wconvh[15 * 128 * 64];      // conv_W bf16 hi/lo
__device__ uint32_t g_wconvl[15 * 128 * 64];
__device__ float g_dinv[KCH * NNODE];
__device__ int   g_cnt[KCH * NNODE];
__device__ int   g_rowptr[KCH * (NNODE + 1)];
__device__ int   g_cursor[KCH * NNODE];
__device__ int   g_bsum[KCH * SCAN_BLOCKS];
__device__ int   g_esrc[NEDGE];
__device__ float g_ecoef[NEDGE];
__device__ float g_pooled[NGROUP * 3 * HID];

// ---------------- bf16 split helpers ----------------------------------------
__device__ __forceinline__ void split_pair(float x, float y, uint32_t& h, uint32_t& l) {
    __nv_bfloat162 hb = __floats2bfloat162_rn(x, y);
    float hx = __bfloat162float(hb.x), hy = __bfloat162float(hb.y);
    __nv_bfloat162 lb = __floats2bfloat162_rn(x - hx, y - hy);
    h = *reinterpret_cast<uint32_t*>(&hb);
    l = *reinterpret_cast<uint32_t*>(&lb);
}

__global__ void prep_pairs(const float* __restrict__ src, uint32_t* __restrict__ dh,
                           uint32_t* __restrict__ dl, int npairs) {
    int i = blockIdx.x * blockDim.x + threadIdx.x;
    if (i >= npairs) return;
    float2 v = *reinterpret_cast<const float2*>(src + (size_t)i * 2);
    uint32_t h, l;
    split_pair(v.x, v.y, h, l);
    dh[i] = h;
    dl[i] = l;
}

// ---------------- CSR build -------------------------------------------------
__global__ void count_kernel(const int* __restrict__ kei) {
    int e = blockIdx.x * blockDim.x + threadIdx.x;
    if (e >= NEDGE) return;
    int chunk = e / EPK;
    int d = kei[NEDGE + e];
    atomicAdd(&g_cnt[chunk * NNODE + d], 1);
}

__global__ void dinv_kernel() {
    int i = blockIdx.x * blockDim.x + threadIdx.x;
    if (i >= KCH * NNODE) return;
    g_dinv[i] = rsqrtf((float)g_cnt[i] + 1.0f);
}

__global__ void scan1_kernel() {
    int ch = blockIdx.y, bx = blockIdx.x, tid = threadIdx.x;
    const int* cnt = g_cnt + ch * NNODE;
    int base = bx * 2048 + tid * 8;
    int tot = 0;
#pragma unroll
    for (int i = 0; i < 8; i++) { int idx = base + i; if (idx < NNODE) tot += cnt[idx]; }
    __shared__ int s[256];
    s[tid] = tot; __syncthreads();
    for (int off = 128; off > 0; off >>= 1) {
        if (tid < off) s[tid] += s[tid + off];
        __syncthreads();
    }
    if (tid == 0) g_bsum[ch * SCAN_BLOCKS + bx] = s[0];
}

__global__ void scan2_kernel() {
    int c = threadIdx.x;
    if (c >= KCH) return;
    int run = 0;
    for (int b = 0; b < SCAN_BLOCKS; b++) {
        int t = g_bsum[c * SCAN_BLOCKS + b];
        g_bsum[c * SCAN_BLOCKS + b] = run;
        run += t;
    }
    g_rowptr[c * (NNODE + 1) + NNODE] = run;
}

__global__ void scan3_kernel() {
    int ch = blockIdx.y, bx = blockIdx.x, tid = threadIdx.x;
    const int* cnt = g_cnt + ch * NNODE;
    int base = bx * 2048 + tid * 8;
    int v[8]; int tot = 0;
#pragma unroll
    for (int i = 0; i < 8; i++) {
        int idx = base + i;
        v[i] = (idx < NNODE) ? cnt[idx] : 0;
        tot += v[i];
    }
    __shared__ int s[256];
    s[tid] = tot; __syncthreads();
    for (int off = 1; off < 256; off <<= 1) {
        int t = (tid >= off) ? s[tid - off] : 0;
        __syncthreads();
        s[tid] += t;
        __syncthreads();
    }
    int excl = s[tid] - tot + g_bsum[ch * SCAN_BLOCKS + bx];
    int* rowp = g_rowptr + ch * (NNODE + 1);
    int* curs = g_cursor + ch * NNODE;
#pragma unroll
    for (int i = 0; i < 8; i++) {
        int idx = base + i;
        if (idx < NNODE) { rowp[idx] = excl; curs[idx] = excl; }
        excl += v[i];
    }
}

__global__ void scatter_kernel(const int* __restrict__ kei) {
    int e = blockIdx.x * blockDim.x + threadIdx.x;
    if (e >= NEDGE) return;
    int chunk = e / EPK;
    int s = kei[e];
    int d = kei[NEDGE + e];
    int pos = atomicAdd(&g_cursor[chunk * NNODE + d], 1);
    g_esrc[(size_t)chunk * EPK + pos] = s;
    g_ecoef[(size_t)chunk * EPK + pos] =
        g_dinv[chunk * NNODE + s] * g_dinv[chunk * NNODE + d];
}

// ---------------- split-bf16 mma.sync GEMM core ------------------------------
// C[M][128] = A[M][K] @ W[128][K]^T (+bias); A,W pre-split bf16 hi/lo.
//   D = Ahi*Whi + Alo*Whi + Ahi*Wlo
// XOR-swizzled smem (quad ^= row&QM): conflict-free fragment LDS.
__device__ __forceinline__ void mma_bf16(float* c, const uint32_t* a,
                                         uint32_t b0, uint32_t b1) {
    asm volatile(
        "mma.sync.aligned.m16n8k16.row.col.f32.bf16.bf16.f32 "
        "{%0,%1,%2,%3}, {%4,%5,%6,%7}, {%8,%9}, {%0,%1,%2,%3};"
        : "+f"(c[0]), "+f"(c[1]), "+f"(c[2]), "+f"(c[3])
        : "r"(a[0]), "r"(a[1]), "r"(a[2]), "r"(a[3]), "r"(b0), "r"(b1));
}

template <int K>
__device__ __forceinline__ void gemm_body(
    const uint32_t* __restrict__ Ah, const uint32_t* __restrict__ Al,
    const uint32_t* __restrict__ Wh, const uint32_t* __restrict__ Wl,
    const float* __restrict__ bias, float* __restrict__ C,
    uint32_t* __restrict__ Ch, uint32_t* __restrict__ Cl, int M, int m0,
    uint32_t* sm) {
    constexpr int RW = K / 2;                      // u32 words per row
    constexpr int NQ = RW / 4;                     // uint4 quads per row
    constexpr int QM = (NQ >= 8) ? 7 : (NQ - 1);   // swizzle mask
    constexpr int NKC = K / 16;

    uint32_t* sWh = sm;                    // 128*RW
    uint32_t* sWl = sWh + 128 * RW;
    uint32_t* sAh = sWl + 128 * RW;        // 64*RW
    uint32_t* sAl = sAh + 64 * RW;

    int tid = threadIdx.x;
    int lane = tid & 31, warp = tid >> 5;
    int wm = warp >> 1, wn = warp & 1;

    for (int idx = tid; idx < 128 * NQ; idx += 256) {
        int r = idx / NQ, q = idx % NQ;
        int dq = q ^ (r & QM);
        *reinterpret_cast<uint4*>(sWh + r * RW + dq * 4) =
            *reinterpret_cast<const uint4*>(Wh + (size_t)r * RW + q * 4);
        *reinterpret_cast<uint4*>(sWl + r * RW + dq * 4) =
            *reinterpret_cast<const uint4*>(Wl + (size_t)r * RW + q * 4);
    }
    for (int idx = tid; idx < 64 * NQ; idx += 256) {
        int r = idx / NQ, q = idx % NQ;
        int row = m0 + r; if (row >= M) row = M - 1;
        int dq = q ^ (r & QM);
        *reinterpret_cast<uint4*>(sAh + r * RW + dq * 4) =
            *reinterpret_cast<const uint4*>(Ah + (size_t)row * RW + q * 4);
        *reinterpret_cast<uint4*>(sAl + r * RW + dq * 4) =
            *reinterpret_cast<const uint4*>(Al + (size_t)row * RW + q * 4);
    }
    __syncthreads();

    float c[8][4];
#pragma unroll
    for (int i = 0; i < 8; i++)
#pragma unroll
        for (int j = 0; j < 4; j++) c[i][j] = 0.f;

    int g = lane >> 2, t = lane & 3;

#define LDW(base, r, w) (base)[(r) * RW + (((((w) >> 2) ^ ((r) & QM))) << 2) + ((w) & 3)]

#pragma unroll
    for (int kc = 0; kc < NKC; kc++) {
        int w0 = kc * 8 + t;
        int w1 = kc * 8 + 4 + t;
        int ra = wm * 16 + g;
        uint32_t ah[4], al[4];
        ah[0] = LDW(sAh, ra, w0);     al[0] = LDW(sAl, ra, w0);
        ah[1] = LDW(sAh, ra + 8, w0); al[1] = LDW(sAl, ra + 8, w0);
        ah[2] = LDW(sAh, ra, w1);     al[2] = LDW(sAl, ra, w1);
        ah[3] = LDW(sAh, ra + 8, w1); al[3] = LDW(sAl, ra + 8, w1);
#pragma unroll
        for (int nt = 0; nt < 8; nt++) {
            int n = wn * 64 + nt * 8 + g;
            uint32_t bh0 = LDW(sWh, n, w0), bh1 = LDW(sWh, n, w1);
            uint32_t bl0 = LDW(sWl, n, w0), bl1 = LDW(sWl, n, w1);
            mma_bf16(c[nt], ah, bh0, bh1);
            mma_bf16(c[nt], al, bh0, bh1);
            mma_bf16(c[nt], ah, bl0, bl1);
        }
    }
#undef LDW

    int r0 = m0 + wm * 16 + g;
    int r1 = r0 + 8;
#pragma unroll
    for (int nt = 0; nt < 8; nt++) {
        int col = wn * 64 + nt * 8 + t * 2;
        float bx = 0.f, by = 0.f;
        if (bias) { bx = bias[col]; by = bias[col + 1]; }
        if (r0 < M) {
            float2 o = make_float2(c[nt][0] + bx, c[nt][1] + by);
            if (C) *reinterpret_cast<float2*>(C + (size_t)r0 * HID + col) = o;
            if (Ch) {
                uint32_t h, l;
                split_pair(o.x, o.y, h, l);
                Ch[(size_t)r0 * 64 + (col >> 1)] = h;
                Cl[(size_t)r0 * 64 + (col >> 1)] = l;
            }
        }
        if (r1 < M) {
            float2 o = make_float2(c[nt][2] + bx, c[nt][3] + by);
            if (C) *reinterpret_cast<float2*>(C + (size_t)r1 * HID + col) = o;
            if (Ch) {
                uint32_t h, l;
                split_pair(o.x, o.y, h, l);
                Ch[(size_t)r1 * 64 + (col >> 1)] = h;
                Cl[(size_t)r1 * 64 + (col >> 1)] = l;
            }
        }
    }
}

// embedding GEMM (K=32): bf16 output only
__global__ __launch_bounds__(256) void gemm_emb(const float* __restrict__ emb_b) {
    extern __shared__ uint32_t sm[];
    gemm_body<IN_DIM>(g_xbh, g_xbl, g_wembh, g_wembl, emb_b,
                      nullptr, g_hbh[0], g_hbl[0], NNODE, blockIdx.x * 64, sm);
}

// batched per-layer conv GEMMs: blockIdx.y = k-1; A = x_l[l-y], C = h1m[y]
__global__ __launch_bounds__(256) void gemm_layer(int l, int ci0) {
    extern __shared__ uint32_t sm[];
    int y = blockIdx.y;
    gemm_body<HID>(g_hbh[l - y], g_hbl[l - y],
                   g_wconvh + (size_t)(ci0 + y) * 128 * 64,
                   g_wconvl + (size_t)(ci0 + y) * 128 * 64,
                   nullptr, g_h1m[y], nullptr, nullptr, NNODE, blockIdx.x * 64, sm);
}

// ---------------- fused per-layer GCN aggregation ----------------------------
// one warp per dst node; loops all k chunks of layer l, accumulates in regs,
// relu + bf16 split once. float out only for the final layer (pool input).
__global__ __launch_bounds__(256) void agg_layer(
    int l, int ci0, const float* __restrict__ conv_b, int write_float) {
    int w = (blockIdx.x * blockDim.x + threadIdx.x) >> 5;
    int lane = threadIdx.x & 31;
    if (w >= NNODE) return;

    float4 tot = make_float4(0.f, 0.f, 0.f, 0.f);
    for (int k = 0; k <= l; k++) {
        const float* h1 = g_h1m[k];
        const int* esrc = g_esrc + (size_t)k * EPK;
        const float* ecoef = g_ecoef + (size_t)k * EPK;
        int beg = g_rowptr[k * (NNODE + 1) + w];
        int end = g_rowptr[k * (NNODE + 1) + w + 1];
        float4 a0 = make_float4(0.f, 0.f, 0.f, 0.f);
        float4 a1 = make_float4(0.f, 0.f, 0.f, 0.f);
        int e = beg;
        for (; e + 1 < end; e += 2) {
            int s0 = __ldg(esrc + e), s1 = __ldg(esrc + e + 1);
            float c0 = __ldg(ecoef + e), c1 = __ldg(ecoef + e + 1);
            float4 v0 = *reinterpret_cast<const float4*>(h1 + (size_t)s0 * HID + lane * 4);
            float4 v1 = *reinterpret_cast<const float4*>(h1 + (size_t)s1 * HID + lane * 4);
            a0.x = fmaf(c0, v0.x, a0.x); a0.y = fmaf(c0, v0.y, a0.y);
            a0.z = fmaf(c0, v0.z, a0.z); a0.w = fmaf(c0, v0.w, a0.w);
            a1.x = fmaf(c1, v1.x, a1.x); a1.y = fmaf(c1, v1.y, a1.y);
            a1.z = fmaf(c1, v1.z, a1.z); a1.w = fmaf(c1, v1.w, a1.w);
        }
        if (e < end) {
            int s0 = __ldg(esrc + e);
            float c0 = __ldg(ecoef + e);
            float4 v0 = *reinterpret_cast<const float4*>(h1 + (size_t)s0 * HID + lane * 4);
            a0.x = fmaf(c0, v0.x, a0.x); a0.y = fmaf(c0, v0.y, a0.y);
            a0.z = fmaf(c0, v0.z, a0.z); a0.w = fmaf(c0, v0.w, a0.w);
        }
        float di = g_dinv[k * NNODE + w];
        float sc = di * di;
        float4 hv = *reinterpret_cast<const float4*>(h1 + (size_t)w * HID + lane * 4);
        float4 bv = *reinterpret_cast<const float4*>(conv_b + (size_t)(ci0 + k) * HID + lane * 4);
        float invk = 1.0f / (float)(k + 1);
        tot.x += (a0.x + a1.x + sc * hv.x + bv.x) * invk;
        tot.y += (a0.y + a1.y + sc * hv.y + bv.y) * invk;
        tot.z += (a0.z + a1.z + sc * hv.z + bv.z) * invk;
        tot.w += (a0.w + a1.w + sc * hv.w + bv.w) * invk;
    }

    float4 r = make_float4(fmaxf(tot.x, 0.f), fmaxf(tot.y, 0.f),
                           fmaxf(tot.z, 0.f), fmaxf(tot.w, 0.f));
    uint32_t* oh = g_hbh[l + 1];
    uint32_t* ol = g_hbl[l + 1];
    uint32_t h0, l0, h1b, l1b;
    split_pair(r.x, r.y, h0, l0);
    split_pair(r.z, r.w, h1b, l1b);
    oh[(size_t)w * 64 + lane * 2] = h0;
    oh[(size_t)w * 64 + lane * 2 + 1] = h1b;
    ol[(size_t)w * 64 + lane * 2] = l0;
    ol[(size_t)w * 64 + lane * 2 + 1] = l1b;
    if (write_float)
        *reinterpret_cast<float4*>(g_x5 + (size_t)w * HID + lane * 4) = r;
}

// ---------------- pooling ----------------------------------------------------
__global__ void pool_kernel(const int* __restrict__ batch,
                            const float* __restrict__ h,
                            float* __restrict__ pooled) {
    int g = blockIdx.x;
    int c = threadIdx.x;
    __shared__ int s_lo, s_hi;
    if (c == 0) {
        int lo = 0, hi = NNODE;
        while (lo < hi) { int m = (lo + hi) >> 1; if (batch[m] < g) lo = m + 1; else hi = m; }
        s_lo = lo;
        int lo2 = lo, hi2 = NNODE;
        while (lo2 < hi2) { int m = (lo2 + hi2) >> 1; if (batch[m] < g + 1) lo2 = m + 1; else hi2 = m; }
        s_hi = lo2;
    }
    __syncthreads();
    int lo = s_lo, hi = s_hi;
    float s = 0.f, mx = -3.402823466e38f;
    for (int i = lo; i < hi; i++) {
        float v = h[(size_t)i * HID + c];
        s += v;
        mx = fmaxf(mx, v);
    }
    float cntf = (float)(hi - lo);
    pooled[g * 384 + c] = s;
    pooled[g * 384 + 128 + c] = mx;
    pooled[g * 384 + 256 + c] = s / fmaxf(cntf, 1.f);
}

// ---------------- MLP head ---------------------------------------------------
__global__ void mlp_kernel(const float* __restrict__ pooled,
                           const float* __restrict__ r1W, const float* __restrict__ r1b,
                           const float* __restrict__ r2W, const float* __restrict__ r2b,
                           float* __restrict__ out) {
    int g = blockIdx.x;
    int j = threadIdx.x;  // 192 threads
    __shared__ float sp[384];
    __shared__ float sh[192];
    for (int t = j; t < 384; t += 192) sp[t] = pooled[g * 384 + t];
    __syncthreads();
    float acc = r1b[j];
    const float* wr = r1W + (size_t)j * 384;
#pragma unroll 4
    for (int t = 0; t < 384; t++) acc = fmaf(sp[t], wr[t], acc);
    sh[j] = acc > 0.f ? acc : 0.01f * acc;
    __syncthreads();
    if (j < OUT_DIMS) {
        float a2 = r2b[j];
        const float* w2 = r2W + (size_t)j * 192;
#pragma unroll 4
        for (int t = 0; t < 192; t++) a2 = fmaf(sh[t], w2[t], a2);
        out[g * OUT_DIMS + j] = a2;
    }
}

// ---------------- launch ----------------------------------------------------
extern "C" void kernel_launch(void* const* d_in, const int* in_sizes, int n_in,
                              void* d_out, int out_size) {
    const float* x      = (const float*)d_in[0];
    const int*   kei    = (const int*)d_in[1];
    const int*   batch  = (const int*)d_in[3];
    const float* emb_W  = (const float*)d_in[4];
    const float* emb_b  = (const float*)d_in[5];
    const float* conv_W = (const float*)d_in[6];
    const float* conv_b = (const float*)d_in[7];
    const float* r1_W   = (const float*)d_in[8];
    const float* r1_b   = (const float*)d_in[9];
    const float* r2_W   = (const float*)d_in[10];
    const float* r2_b   = (const float*)d_in[11];
    float* out = (float*)d_out;

    float *x5, *pooled;
    int* cntp;
    uint32_t *xbh, *xbl, *wembh, *wembl, *wconvh, *wconvl;
    cudaGetSymbolAddress((void**)&x5, g_x5);
    cudaGetSymbolAddress((void**)&pooled, g_pooled);
    cudaGetSymbolAddress((void**)&cntp, g_cnt);
    cudaGetSymbolAddress((void**)&xbh, g_xbh);
    cudaGetSymbolAddress((void**)&xbl, g_xbl);
    cudaGetSymbolAddress((void**)&wembh, g_wembh);
    cudaGetSymbolAddress((void**)&wembl, g_wembl);
    cudaGetSymbolAddress((void**)&wconvh, g_wconvh);
    cudaGetSymbolAddress((void**)&wconvl, g_wconvl);

    const int SMEM128 = (128 * 64 * 2 + 64 * 64 * 2) * 4;   // 98304 B
    const int SMEM32  = (128 * 16 * 2 + 64 * 16 * 2) * 4;   // 24576 B
    cudaFuncSetAttribute(gemm_layer, cudaFuncAttributeMaxDynamicSharedMemorySize, SMEM128);
    cudaFuncSetAttribute(gemm_emb, cudaFuncAttributeMaxDynamicSharedMemorySize, SMEM32);

    // operand prep (bf16 hi/lo splits)
    prep_pairs<<<(NNODE * 16 + 255) / 256, 256>>>(x, xbh, xbl, NNODE * 16);
    prep_pairs<<<(128 * 16 + 255) / 256, 256>>>(emb_W, wembh, wembl, 128 * 16);
    prep_pairs<<<(15 * 128 * 64 + 255) / 256, 256>>>(conv_W, wconvh, wconvl, 15 * 128 * 64);

    // CSR build (per launch; deterministic work)
    cudaMemsetAsync(cntp, 0, sizeof(int) * KCH * NNODE);
    count_kernel<<<(NEDGE + 255) / 256, 256>>>(kei);
    dinv_kernel<<<(KCH * NNODE + 255) / 256, 256>>>();
    dim3 sg(SCAN_BLOCKS, KCH);
    scan1_kernel<<<sg, 256>>>();
    scan2_kernel<<<1, 32>>>();
    scan3_kernel<<<sg, 256>>>();
    scatter_kernel<<<(NEDGE + 255) / 256, 256>>>(kei);

    const int mtiles = (NNODE + 63) / 64;           // 782
    const int agg_grid = (NNODE * 32 + 255) / 256;

    // embedding: x_l[0] = x @ emb_W^T + emb_b (bf16 hi/lo only)
    gemm_emb<<<mtiles, 256, SMEM32>>>(emb_b);

    for (int l = 0; l < 5; l++) {
        int ci0 = l * (l + 1) / 2;
        dim3 gg(mtiles, l + 1);
        gemm_layer<<<gg, 256, SMEM128>>>(l, ci0);
        agg_layer<<<agg_grid, 256>>>(l, ci0, conv_b, (l == 4) ? 1 : 0);
    }

    pool_kernel<<<NGROUP, HID>>>(batch, x5, pooled);
    mlp_kernel<<<NGROUP, 192>>>(pooled, r1_W, r1_b, r2_W, r2_b, out);
}